// round 1
// baseline (speedup 1.0000x reference)
#include <cuda_runtime.h>
#include <cstdint>
#include <math.h>

// Problem dims
#define T_TOK 8192
#define DIM   1024
#define NEXP  8
#define H1DIM 4096
#define H2DIM 2048
#define TPAD  9216          // 8192 + 8*128 worst-case padding
#define MAX_TILES 72        // TPAD/128

// GEMM tile config
#define BM 128
#define BN 128
#define BK 32
#define A_STRIDE 36         // floats; (4m+k)%32 distinct -> conflict-free LDS frags
#define B_STRIDE 136        // floats; (8k+n)%32 distinct -> conflict-free LDS frags
#define A_SZ (BM * A_STRIDE)        // 4608 floats
#define B_SZ (BK * B_STRIDE)        // 4352 floats
#define STAGE_SZ (A_SZ + B_SZ)      // 8960 floats
#define SMEM_BYTES (2 * STAGE_SZ * 4)  // 71680 B (double-buffered)

// ---------------- device scratch (alloc-free rule: __device__ globals) -------
__device__ int g_expert_id[T_TOK];
__device__ int g_counts[NEXP];
__device__ int g_cursor[NEXP];
__device__ int g_offsets[NEXP];
__device__ int g_tok[TPAD];                    // token idx per padded row, -1 = pad
__device__ int g_tile_expert[MAX_TILES];
__device__ int g_tile_row[MAX_TILES];
__device__ float g_h1[(size_t)TPAD * H1DIM];   // 151 MB
__device__ float g_h2[(size_t)TPAD * H2DIM];   // 75.5 MB

// ---------------- small helpers ---------------------------------------------
__device__ __forceinline__ uint32_t f2tf(float f) {
    uint32_t r;
    asm("cvt.rna.tf32.f32 %0, %1;" : "=r"(r) : "f"(f));
    return r;
}

__device__ __forceinline__ void mma8(float* c, const uint32_t* a, const uint32_t* b) {
    asm volatile(
        "mma.sync.aligned.m16n8k8.row.col.f32.tf32.tf32.f32 "
        "{%0,%1,%2,%3}, {%4,%5,%6,%7}, {%8,%9}, {%0,%1,%2,%3};\n"
        : "+f"(c[0]), "+f"(c[1]), "+f"(c[2]), "+f"(c[3])
        : "r"(a[0]), "r"(a[1]), "r"(a[2]), "r"(a[3]), "r"(b[0]), "r"(b[1]));
}

__device__ __forceinline__ void cpa16(uint32_t smem_addr, const void* gptr, int src_sz) {
    asm volatile("cp.async.cg.shared.global [%0], [%1], 16, %2;\n"
                 :: "r"(smem_addr), "l"(gptr), "r"(src_sz));
}
__device__ __forceinline__ void cp_commit() { asm volatile("cp.async.commit_group;\n"); }
template <int N>
__device__ __forceinline__ void cp_wait() { asm volatile("cp.async.wait_group %0;\n" :: "n"(N)); }

__device__ __forceinline__ float gelu_exact(float v) {
    return 0.5f * v * (1.0f + erff(v * 0.70710678118654752f));
}

// ---------------- phase 0: init ---------------------------------------------
__global__ void init_kernel() {
    int i = blockIdx.x * blockDim.x + threadIdx.x;
    if (i < TPAD) g_tok[i] = -1;
    if (i < NEXP) { g_counts[i] = 0; g_cursor[i] = 0; }
}

// ---------------- phase 1: router (fp32 exact-ish, warp per token) ----------
__global__ void router_kernel(const float* __restrict__ x,
                              const float* __restrict__ Wr,
                              const float* __restrict__ br) {
    __shared__ float s_wr[DIM * NEXP];
    __shared__ float s_br[NEXP];
    int tid = threadIdx.x;
    for (int i = tid; i < DIM * NEXP / 4; i += 256)
        ((float4*)s_wr)[i] = ((const float4*)Wr)[i];
    if (tid < NEXP) s_br[tid] = br[tid];
    __syncthreads();

    int warp = tid >> 5, lane = tid & 31;
    int t = blockIdx.x * 8 + warp;   // grid = T/8 blocks of 8 warps

    float acc[NEXP];
#pragma unroll
    for (int e = 0; e < NEXP; e++) acc[e] = 0.0f;

    const float* xr = x + (size_t)t * DIM;
    for (int d = lane; d < DIM; d += 32) {
        float xv = xr[d];
#pragma unroll
        for (int e = 0; e < NEXP; e++) acc[e] += xv * s_wr[d * NEXP + e];
    }
#pragma unroll
    for (int e = 0; e < NEXP; e++)
        for (int o = 16; o; o >>= 1) acc[e] += __shfl_down_sync(0xffffffffu, acc[e], o);

    if (lane == 0) {
        float best = acc[0] + s_br[0];
        int bi = 0;
        for (int e = 1; e < NEXP; e++) {
            float v = acc[e] + s_br[e];
            if (v > best) { best = v; bi = e; }   // strict > = first-max, matches argmax
        }
        g_expert_id[t] = bi;
        atomicAdd(&g_counts[bi], 1);
    }
}

// ---------------- phase 2: padded offsets + tile schedule (serial, tiny) ----
__global__ void schedule_kernel() {
    if (threadIdx.x == 0 && blockIdx.x == 0) {
        int off = 0, t = 0;
        for (int e = 0; e < NEXP; e++) {
            g_offsets[e] = off;
            int c = g_counts[e];
            int tiles = (c + BM - 1) >> 7;
            for (int i = 0; i < tiles; i++) {
                g_tile_expert[t] = e;
                g_tile_row[t] = off + i * BM;
                t++;
            }
            off += tiles << 7;
        }
        for (; t < MAX_TILES; t++) { g_tile_expert[t] = -1; g_tile_row[t] = 0; }
    }
}

// ---------------- phase 3: scatter tokens into grouped order ----------------
__global__ void scatter_kernel() {
    int t = blockIdx.x * blockDim.x + threadIdx.x;
    if (t < T_TOK) {
        int e = g_expert_id[t];
        int pos = g_offsets[e] + atomicAdd(&g_cursor[e], 1);
        g_tok[pos] = t;
    }
}

// ---------------- phase 4: grouped GEMM + bias + (GELU) ---------------------
// A: [rows, K] (gathered via g_tok if GATHER_A, else padded rows directly)
// W: [E, K, N] row-major; bias: [E, N]
// Out: padded activations, or scattered to d_out if SCATTER_OUT
template <bool GATHER_A, bool DO_GELU, bool SCATTER_OUT>
__global__ void __launch_bounds__(256, 2)
moe_gemm(const float* __restrict__ A, const float* __restrict__ W,
         const float* __restrict__ bias, float* __restrict__ Out,
         int K, int N, int lda, int ldo) {
    int by = blockIdx.y;
    int e = g_tile_expert[by];
    if (e < 0) return;
    int row0 = g_tile_row[by];
    int n0 = blockIdx.x * BN;

    extern __shared__ float smem[];
    __shared__ int s_tok[BM];

    int tid = threadIdx.x;
    if (GATHER_A || SCATTER_OUT) {
        if (tid < BM) s_tok[tid] = g_tok[row0 + tid];
        __syncthreads();
    }

    const float* We = W + (size_t)e * K * N + n0;
    const float* be = bias + (size_t)e * N + n0;

    uint32_t smem_base = (uint32_t)__cvta_generic_to_shared(smem);

    auto load_tile = [&](int stage, int kt) {
        uint32_t a_s = smem_base + stage * (STAGE_SZ * 4);
        uint32_t b_s = a_s + A_SZ * 4;
        int kk = kt * BK;
        // A tile: 128 rows x 32 floats; 8 lanes per row -> 128B coalesced
#pragma unroll
        for (int i = 0; i < 4; i++) {
            int idx = tid + i * 256;
            int r = idx >> 3;
            int c = (idx & 7) << 2;
            const float* src;
            int sz = 16;
            if (GATHER_A) {
                int tok = s_tok[r];
                int trow = tok < 0 ? 0 : tok;
                src = A + (size_t)trow * lda + kk + c;
                sz = tok < 0 ? 0 : 16;   // zero-fill pad rows
            } else {
                src = A + (size_t)(row0 + r) * lda + kk + c;
            }
            cpa16(a_s + (uint32_t)(r * A_STRIDE + c) * 4, src, sz);
        }
        // B tile: 32 k-rows x 128 cols; 32 lanes consecutive -> 512B coalesced
#pragma unroll
        for (int i = 0; i < 4; i++) {
            int idx = tid + i * 256;
            int r = idx >> 5;
            int c = (idx & 31) << 2;
            const float* src = We + (size_t)(kk + r) * N + c;
            cpa16(b_s + (uint32_t)(r * B_STRIDE + c) * 4, src, 16);
        }
    };

    float acc[4][4][4];
#pragma unroll
    for (int mf = 0; mf < 4; mf++)
#pragma unroll
        for (int nf = 0; nf < 4; nf++)
#pragma unroll
            for (int i = 0; i < 4; i++) acc[mf][nf][i] = 0.0f;

    int wid = tid >> 5, lane = tid & 31;
    int wm = (wid & 1) * 64;     // warp m offset (2 warps in m)
    int wn = (wid >> 1) * 32;    // warp n offset (4 warps in n)
    int mq = lane >> 2, kq = lane & 3;

    int nk = K / BK;
    load_tile(0, 0);
    cp_commit();

    for (int kt = 0; kt < nk; ++kt) {
        if (kt + 1 < nk) load_tile((kt + 1) & 1, kt + 1);
        cp_commit();
        cp_wait<1>();
        __syncthreads();

        const float* As = smem + (kt & 1) * STAGE_SZ;
        const float* Bs = As + A_SZ;

#pragma unroll
        for (int k8 = 0; k8 < 4; ++k8) {
            int kb = k8 * 8;
            uint32_t af[4][4];
#pragma unroll
            for (int mf = 0; mf < 4; mf++) {
                int m = wm + mf * 16 + mq;
                af[mf][0] = f2tf(As[m * A_STRIDE + kb + kq]);
                af[mf][1] = f2tf(As[(m + 8) * A_STRIDE + kb + kq]);
                af[mf][2] = f2tf(As[m * A_STRIDE + kb + kq + 4]);
                af[mf][3] = f2tf(As[(m + 8) * A_STRIDE + kb + kq + 4]);
            }
            uint32_t bf[4][2];
#pragma unroll
            for (int nf = 0; nf < 4; nf++) {
                int n = wn + nf * 8 + mq;
                bf[nf][0] = f2tf(Bs[(kb + kq) * B_STRIDE + n]);
                bf[nf][1] = f2tf(Bs[(kb + kq + 4) * B_STRIDE + n]);
            }
#pragma unroll
            for (int mf = 0; mf < 4; mf++)
#pragma unroll
                for (int nf = 0; nf < 4; nf++)
                    mma8(acc[mf][nf], af[mf], bf[nf]);
        }
        __syncthreads();
    }

    // epilogue: bias + activation + store (float2, n-pairs)
#pragma unroll
    for (int mf = 0; mf < 4; mf++) {
#pragma unroll
        for (int nf = 0; nf < 4; nf++) {
            int m = wm + mf * 16 + mq;
            int nc = wn + nf * 8 + kq * 2;
            float b0 = be[nc], b1 = be[nc + 1];
            float v00 = acc[mf][nf][0] + b0, v01 = acc[mf][nf][1] + b1;
            float v10 = acc[mf][nf][2] + b0, v11 = acc[mf][nf][3] + b1;
            if (DO_GELU) {
                v00 = gelu_exact(v00); v01 = gelu_exact(v01);
                v10 = gelu_exact(v10); v11 = gelu_exact(v11);
            }
            size_t col = (size_t)n0 + nc;
            if (SCATTER_OUT) {
                int t0 = s_tok[m];
                if (t0 >= 0)
                    *(float2*)&Out[(size_t)t0 * ldo + col] = make_float2(v00, v01);
                int t1 = s_tok[m + 8];
                if (t1 >= 0)
                    *(float2*)&Out[(size_t)t1 * ldo + col] = make_float2(v10, v11);
            } else {
                *(float2*)&Out[(size_t)(row0 + m) * ldo + col] = make_float2(v00, v01);
                *(float2*)&Out[(size_t)(row0 + m + 8) * ldo + col] = make_float2(v10, v11);
            }
        }
    }
}

// ---------------- launch ------------------------------------------------------
extern "C" void kernel_launch(void* const* d_in, const int* in_sizes, int n_in,
                              void* d_out, int out_size) {
    const float* x  = (const float*)d_in[0];
    const float* Wr = (const float*)d_in[1];
    const float* br = (const float*)d_in[2];
    const float* W1 = (const float*)d_in[3];
    const float* b1 = (const float*)d_in[4];
    const float* W2 = (const float*)d_in[5];
    const float* b2 = (const float*)d_in[6];
    const float* W3 = (const float*)d_in[7];
    const float* b3 = (const float*)d_in[8];
    float* out = (float*)d_out;

    float *h1, *h2;
    cudaGetSymbolAddress((void**)&h1, g_h1);
    cudaGetSymbolAddress((void**)&h2, g_h2);

    cudaFuncSetAttribute((const void*)moe_gemm<true, true, false>,
                         cudaFuncAttributeMaxDynamicSharedMemorySize, SMEM_BYTES);
    cudaFuncSetAttribute((const void*)moe_gemm<false, true, false>,
                         cudaFuncAttributeMaxDynamicSharedMemorySize, SMEM_BYTES);
    cudaFuncSetAttribute((const void*)moe_gemm<false, false, true>,
                         cudaFuncAttributeMaxDynamicSharedMemorySize, SMEM_BYTES);

    init_kernel<<<(TPAD + 255) / 256, 256>>>();
    router_kernel<<<T_TOK / 8, 256>>>(x, Wr, br);
    schedule_kernel<<<1, 32>>>();
    scatter_kernel<<<(T_TOK + 255) / 256, 256>>>();

    // x @ W1 + b1 -> gelu -> h1   (gathered rows)
    moe_gemm<true, true, false><<<dim3(H1DIM / BN, MAX_TILES), 256, SMEM_BYTES>>>(
        x, W1, b1, h1, DIM, H1DIM, DIM, H1DIM);
    // h1 @ W2 + b2 -> gelu -> h2
    moe_gemm<false, true, false><<<dim3(H2DIM / BN, MAX_TILES), 256, SMEM_BYTES>>>(
        h1, W2, b2, h2, H1DIM, H2DIM, H1DIM, H2DIM);
    // h2 @ W3 + b3 -> scatter to out
    moe_gemm<false, false, true><<<dim3(DIM / BN, MAX_TILES), 256, SMEM_BYTES>>>(
        h2, W3, b3, out, H2DIM, DIM, H2DIM, DIM);
}